// round 12
// baseline (speedup 1.0000x reference)
#include <cuda_runtime.h>
#include <cstdint>
#include <cstddef>

#define B_  4
#define T_  2048
#define C_  2048
#define H_  16
#define HD_ 128

// ---------------- scratch (static __device__ — no allocations allowed) ----------
__device__ float g_qkv[(size_t)B_ * T_ * 3 * C_];          // [B*T, 3C]
__device__ float g_q  [(size_t)B_ * H_ * T_ * HD_];        // [B,H,T,HD] tf32, pre-scaled
__device__ float g_khi[(size_t)B_ * H_ * T_ * HD_];        // K hi (tf32)
__device__ float g_klo[(size_t)B_ * H_ * T_ * HD_];        // K lo (tf32 of residual)
__device__ float g_v  [(size_t)B_ * H_ * T_ * HD_];        // V (tf32-rounded)
__device__ float g_vt [(size_t)B_ * H_ * HD_ * T_];        // V^T [B,H,HD,T]
__device__ float g_y[(size_t)B_ * T_ * C_];                // attention out (tf32-rounded)
__device__ float g_xtf[(size_t)B_ * T_ * C_];              // x rounded to tf32
__device__ float g_wqkvT[(size_t)3 * C_ * C_];             // Wqkv^T  [3C, C] (tf32)
__device__ float g_wprojT[(size_t)C_ * C_];                // Wproj^T [C, C] (tf32)

// ---------------- small helpers -------------------------------------------------
__device__ __forceinline__ uint32_t f2tf(float x) {
    uint32_t u;
    asm("cvt.rna.tf32.f32 %0, %1;" : "=r"(u) : "f"(x));
    return u;
}
__device__ __forceinline__ float f2tf_f(float x) { return __uint_as_float(f2tf(x)); }

__device__ __forceinline__ void mma_tf32(float* d, const uint32_t* a,
                                         const uint32_t* b) {
    asm volatile(
        "mma.sync.aligned.m16n8k8.row.col.f32.tf32.tf32.f32 "
        "{%0,%1,%2,%3}, {%4,%5,%6,%7}, {%8,%9}, {%0,%1,%2,%3};"
        : "+f"(d[0]), "+f"(d[1]), "+f"(d[2]), "+f"(d[3])
        : "r"(a[0]), "r"(a[1]), "r"(a[2]), "r"(a[3]), "r"(b[0]), "r"(b[1]));
}
__device__ __forceinline__ uint32_t smem_u32(const void* p) {
    uint32_t a;
    asm("{ .reg .u64 t; cvta.to.shared.u64 t, %1; cvt.u32.u64 %0, t; }"
        : "=r"(a) : "l"(p));
    return a;
}
// ldmatrix x4: loads four 8x4-f32 blocks; per-lane addr = row of matrix (lane/8)
__device__ __forceinline__ void ldsm4(uint32_t* r, uint32_t addr) {
    asm volatile("ldmatrix.sync.aligned.m8n8.x4.shared.b16 {%0,%1,%2,%3}, [%4];"
                 : "=r"(r[0]), "=r"(r[1]), "=r"(r[2]), "=r"(r[3]) : "r"(addr));
}
__device__ __forceinline__ void cp16(uint32_t dst, const void* src) {
    asm volatile("cp.async.cg.shared.global [%0], [%1], 16;"
                 :: "r"(dst), "l"(src) : "memory");
}
__device__ __forceinline__ void cp_commit() {
    asm volatile("cp.async.commit_group;" ::: "memory");
}
template <int N>
__device__ __forceinline__ void cp_wait() {
    asm volatile("cp.async.wait_group %0;" :: "n"(N) : "memory");
}
// FFMA-pipe exp (keeps MUFU free; poly rel err ~2e-6)
__device__ __forceinline__ float expf_fast(float x) {
    float y = fmaxf(x, -60.f) * 1.4426950408889634f;
    float nf;
    asm("cvt.rni.f32.f32 %0, %1;" : "=f"(nf) : "f"(y));
    float f = y - nf;
    float p =              1.3333558e-3f;
    p = fmaf(p, f, 9.6181291e-3f);
    p = fmaf(p, f, 5.5504109e-2f);
    p = fmaf(p, f, 2.4022651e-1f);
    p = fmaf(p, f, 6.9314718e-1f);
    p = fmaf(p, f, 1.0f);
    return __int_as_float(__float_as_int(p) + (((int)nf) << 23));
}

// ===================== TF32 mma.sync GEMM (cp.async 4-stage + ldmatrix) =========
// Copy issue placed AFTER the MMA block (round-10 order): LDSM fragment loads
// must hit the LSU queue before the LDGSTS prefetch batch, or MMAs stall.
#define APITCH 20
#define ABUF_FLOATS (128 * APITCH)
#define BBUF_FLOATS (256 * APITCH)
#define BUF_FLOATS  (ABUF_FLOATS + BBUF_FLOATS)
#define STAGES 4
#define GSM_BYTES (STAGES * BUF_FLOATS * 4)

__global__ __launch_bounds__(256, 1) void gemm_tf32(
    const float* __restrict__ A, const float* __restrict__ Bt,
    float* __restrict__ Cm, int M, int N, int K)
{
    extern __shared__ float sm[];
    const uint32_t sbase = smem_u32(sm);
    const int tid  = threadIdx.x;
    const int wid  = tid >> 5;
    const int lane = tid & 31;
    const int g    = lane >> 2;
    const int c    = lane & 3;
    const int warp_m = wid & 1;
    const int warp_n = wid >> 1;

    const size_t m0 = (size_t)blockIdx.x * 128;
    const size_t n0 = (size_t)blockIdx.y * 256;

    const int aoff = (warp_m * 64 + (lane & 7) + ((lane >> 3) & 1) * 8) * APITCH
                   + ((lane >> 4) & 1) * 4;
    const int boff = (warp_n * 64 + (lane & 7) + ((lane >> 4) & 1) * 8) * APITCH
                   + ((lane >> 3) & 1) * 4;

    const int ar[2]  = { (tid + 0)   >> 2, (tid + 256) >> 2 };
    const int akk[2] = { ((tid + 0)   & 3) << 2, ((tid + 256) & 3) << 2 };
    int br[4], bkk[4];
    #pragma unroll
    for (int j = 0; j < 4; j++) {
        br[j]  = (tid + j * 256) >> 2;
        bkk[j] = ((tid + j * 256) & 3) << 2;
    }

    float acc[4][8][4];
    #pragma unroll
    for (int mi = 0; mi < 4; mi++)
        #pragma unroll
        for (int ni = 0; ni < 8; ni++)
            #pragma unroll
            for (int q = 0; q < 4; q++) acc[mi][ni][q] = 0.f;

    const int niter = K >> 4;

    auto issue = [&](int it) {
        const int k0 = it << 4;
        const uint32_t As = sbase + (uint32_t)(it & (STAGES - 1)) * (BUF_FLOATS * 4);
        const uint32_t Bs = As + ABUF_FLOATS * 4;
        #pragma unroll
        for (int j = 0; j < 2; j++)
            cp16(As + (ar[j] * APITCH + akk[j]) * 4,
                 A + (m0 + ar[j]) * K + k0 + akk[j]);
        #pragma unroll
        for (int j = 0; j < 4; j++)
            cp16(Bs + (br[j] * APITCH + bkk[j]) * 4,
                 Bt + (n0 + br[j]) * K + k0 + bkk[j]);
    };

    #pragma unroll
    for (int s = 0; s < STAGES - 1; s++) {
        if (s < niter) issue(s);
        cp_commit();
    }

    for (int it = 0; it < niter; ++it) {
        cp_wait<STAGES - 2>();
        __syncthreads();

        const uint32_t As_u = sbase + (uint32_t)(it & (STAGES - 1)) * (BUF_FLOATS * 4);
        const uint32_t Bs_u = As_u + ABUF_FLOATS * 4;
        #pragma unroll
        for (int ks = 0; ks < 2; ks++) {
            uint32_t af[4][4], bf[4][4];
            #pragma unroll
            for (int mi = 0; mi < 4; mi++)
                ldsm4(af[mi], As_u + (aoff + mi * 16 * APITCH + ks * 8) * 4);
            #pragma unroll
            for (int np = 0; np < 4; np++)
                ldsm4(bf[np], Bs_u + (boff + np * 16 * APITCH + ks * 8) * 4);
            #pragma unroll
            for (int mi = 0; mi < 4; mi++)
                #pragma unroll
                for (int ni = 0; ni < 8; ni++)
                    mma_tf32(acc[mi][ni], af[mi], &bf[ni >> 1][(ni & 1) * 2]);
        }

        // issue next stage AFTER compute (LDSMs first in the LSU queue)
        if (it + STAGES - 1 < niter) issue(it + STAGES - 1);
        cp_commit();
    }

    #pragma unroll
    for (int mi = 0; mi < 4; mi++) {
        const size_t row0 = m0 + warp_m * 64 + mi * 16 + g;
        #pragma unroll
        for (int ni = 0; ni < 8; ni++) {
            const size_t col = n0 + warp_n * 64 + ni * 8 + 2 * c;
            *(float2*)(Cm + row0 * N + col) =
                make_float2(acc[mi][ni][0], acc[mi][ni][1]);
            *(float2*)(Cm + (row0 + 8) * N + col) =
                make_float2(acc[mi][ni][2], acc[mi][ni][3]);
        }
    }
}

// ---------------- tf32 pre-round ------------------------------------------------
__global__ __launch_bounds__(256) void tf32_round_kernel(
    const float* __restrict__ in, float* __restrict__ out)
{
    int i = blockIdx.x * 256 + threadIdx.x;
    float4 v = ((const float4*)in)[i];
    v.x = f2tf_f(v.x); v.y = f2tf_f(v.y);
    v.z = f2tf_f(v.z); v.w = f2tf_f(v.w);
    ((float4*)out)[i] = v;
}

// ---------------- transpose + tf32 round ---------------------------------------
__global__ __launch_bounds__(256) void transpose_kernel(
    const float* __restrict__ in, float* __restrict__ out, int R, int Cc)
{
    __shared__ float tile[32][33];
    int c0 = blockIdx.x * 32, r0 = blockIdx.y * 32;
    int tx = threadIdx.x & 31, ty = threadIdx.x >> 5;
    #pragma unroll
    for (int j = 0; j < 4; j++)
        tile[ty + j * 8][tx] = in[(size_t)(r0 + ty + j * 8) * Cc + c0 + tx];
    __syncthreads();
    #pragma unroll
    for (int j = 0; j < 4; j++)
        out[(size_t)(c0 + ty + j * 8) * R + r0 + tx] = f2tf_f(tile[tx][ty + j * 8]);
}

// ---------------- batched V transpose: v[bh][t][d] -> vt[bh][d][t] -------------
__global__ __launch_bounds__(256) void vtrans_kernel(
    const float* __restrict__ v, float* __restrict__ vt)
{
    __shared__ float tile[32][33];
    const size_t base = (size_t)blockIdx.z * T_ * HD_;
    int t0 = blockIdx.x * 32, d0 = blockIdx.y * 32;
    int tx = threadIdx.x & 31, ty = threadIdx.x >> 5;
    #pragma unroll
    for (int j = 0; j < 4; j++)
        tile[ty + j * 8][tx] = v[base + (size_t)(t0 + ty + j * 8) * HD_ + d0 + tx];
    __syncthreads();
    #pragma unroll
    for (int j = 0; j < 4; j++)
        vt[base + (size_t)(d0 + ty + j * 8) * T_ + t0 + tx] = tile[tx][ty + j * 8];
}

// ---------------- RoPE: qkv -> q(scaled,tf32), khi, klo, v(tf32) ----------------
__global__ __launch_bounds__(256) void rope_kernel(
    const float* __restrict__ qkv, const float* __restrict__ rope,
    float* __restrict__ q, float* __restrict__ khi,
    float* __restrict__ klo, float* __restrict__ v)
{
    int idx = blockIdx.x * 256 + threadIdx.x;
    int p = idx & 63;
    int h = (idx >> 6) & 15;
    int t = (idx >> 10) & 2047;
    int b = idx >> 21;
    const float scale = 0.08838834764831845f;   // 1/sqrt(128)

    float2 cs = ((const float2*)rope)[t * 64 + p];
    size_t base_in = ((size_t)(b * T_ + t)) * (3 * C_) + h * HD_ + p * 2;
    float2 qv = *(const float2*)(qkv + base_in);
    float2 kv = *(const float2*)(qkv + base_in + C_);
    float2 vv = *(const float2*)(qkv + base_in + 2 * C_);

    float2 qo = make_float2((qv.x * cs.x - qv.y * cs.y) * scale,
                            (qv.y * cs.x + qv.x * cs.y) * scale);
    float2 ko = make_float2(kv.x * cs.x - kv.y * cs.y, kv.y * cs.x + kv.x * cs.y);

    float2 qr  = make_float2(f2tf_f(qo.x), f2tf_f(qo.y));
    float2 khv = make_float2(f2tf_f(ko.x), f2tf_f(ko.y));
    float2 klv = make_float2(f2tf_f(ko.x - khv.x), f2tf_f(ko.y - khv.y));
    float2 vr  = make_float2(f2tf_f(vv.x), f2tf_f(vv.y));

    size_t base_out = ((size_t)((b * H_ + h) * T_ + t)) * HD_ + p * 2;
    *(float2*)(q   + base_out) = qr;
    *(float2*)(khi + base_out) = khv;
    *(float2*)(klo + base_out) = klv;
    *(float2*)(v   + base_out) = vr;
}

// ================== Tensor-core flash attention (tf32, causal) ==================
// CTA: 128 q-rows, 8 warps x 16 rows, 256 threads. kt tiles of 32 keys.
// QK^T = Q*Khi + Q*Klo (split-K precision). PV single tf32 MMA.
// K frags AND V^T frags via ldmatrix.x4 (pitch 132 / 36 -> conflict-free).
// KV copy issue at END of loop (round-10 LSU ordering).
#define KV_TILE_F   (32 * 132)                  // 4224 floats (Khi, Klo each)
#define VT_TILE_F   (128 * 36)                  // 4608 floats (V^T: [dim][key])
#define KV_STRIDE_F (2 * KV_TILE_F + VT_TILE_F) // 13056 floats per stage
#define ASM_BYTES   (3 * KV_STRIDE_F * 4)       // 156672 bytes

__global__ __launch_bounds__(256, 1) void attn_tc(
    const float* __restrict__ Qg, const float* __restrict__ Khig,
    const float* __restrict__ Klog, const float* __restrict__ Vtg,
    float* __restrict__ Y)
{
    extern __shared__ float smn[];
    const uint32_t sbase = smem_u32(smn);
    const int qt = (int)gridDim.x - 1 - (int)blockIdx.x;   // heavy tiles first
    const int bh = blockIdx.y;
    const int b = bh >> 4, h = bh & 15;
    const int tid = threadIdx.x;
    const int w = tid >> 5, lane = tid & 31, g = lane >> 2, c = lane & 3;
    const size_t head = (size_t)bh * T_ * HD_;

    const int koff = ((lane & 7) + ((lane >> 4) & 1) * 8) * 132
                   + ((lane >> 3) & 1) * 4;
    const int voff = ((lane & 7) + ((lane >> 4) & 1) * 8) * 36
                   + ((lane >> 3) & 1) * 4;

    // ---- stage Q tile (already tf32+scaled) into smem pitch 132, extract frags
    {
        const float4* Qt = (const float4*)(Qg + head + (size_t)qt * 128 * HD_);
        for (int i = tid; i < 128 * 32; i += 256) {
            int r = i >> 5, d4 = (i & 31) << 2;
            float4 qv = Qt[i];
            float* dst = smn + r * 132 + d4;
            dst[0] = qv.x; dst[1] = qv.y; dst[2] = qv.z; dst[3] = qv.w;
        }
    }
    __syncthreads();
    uint32_t qf[16][4];
    {
        const float* q0 = smn + (w * 16 + g) * 132 + c;
        #pragma unroll
        for (int ks = 0; ks < 16; ks++) {
            qf[ks][0] = __float_as_uint(q0[ks * 8]);
            qf[ks][1] = __float_as_uint(q0[ks * 8 + 8 * 132]);
            qf[ks][2] = __float_as_uint(q0[ks * 8 + 4]);
            qf[ks][3] = __float_as_uint(q0[ks * 8 + 8 * 132 + 4]);
        }
    }
    __syncthreads();

    float oacc[16][4];
    #pragma unroll
    for (int i = 0; i < 16; i++) {
        oacc[i][0] = 0.f; oacc[i][1] = 0.f; oacc[i][2] = 0.f; oacc[i][3] = 0.f;
    }
    float m0v = -1e30f, m1v = -1e30f, l0 = 0.f, l1 = 0.f;

    const int nkt = qt * 4 + 4;
    const int cr = tid >> 3;              // K copy row 0..31
    const int cc = (tid & 7) << 2;        // K copy col base (floats)
    const int vr = tid >> 1;              // Vt copy row 0..127
    const int vc = (tid & 1) << 4;        // Vt copy col base (floats)

    auto kvissue = [&](int kt) {
        uint32_t stg = sbase + (uint32_t)(kt % 3) * (KV_STRIDE_F * 4);
        uint32_t dstb = stg + cr * (132 * 4);
        size_t srcb = head + ((size_t)kt * 32 + cr) * HD_;
        #pragma unroll
        for (int ch = 0; ch < 4; ch++) {
            uint32_t dst = dstb + (cc + ch * 32) * 4;
            size_t src = srcb + cc + ch * 32;
            cp16(dst,                 Khig + src);
            cp16(dst + KV_TILE_F * 4, Klog + src);
        }
        uint32_t vdstb = stg + 2 * KV_TILE_F * 4 + vr * (36 * 4);
        size_t vsrcb = head + (size_t)vr * T_ + (size_t)kt * 32;
        #pragma unroll
        for (int ch = 0; ch < 4; ch++)
            cp16(vdstb + (vc + ch * 4) * 4, Vtg + vsrcb + vc + ch * 4);
    };
    kvissue(0); cp_commit();
    if (nkt > 1) kvissue(1);
    cp_commit();

    const int rg0 = qt * 128 + w * 16 + g;
    const int rg8 = rg0 + 8;

    for (int kt = 0; kt < nkt; kt++) {
        cp_wait<1>();
        __syncthreads();
        const uint32_t Khs_u = sbase + (uint32_t)(kt % 3) * (KV_STRIDE_F * 4);
        const uint32_t Kls_u = Khs_u + KV_TILE_F * 4;
        const uint32_t Vt_u  = Khs_u + 2 * KV_TILE_F * 4;

        // ---- S = Q*Khi + Q*Klo  (16x32 per warp), K frags via ldmatrix
        float sacc[4][4];
        #pragma unroll
        for (int nt = 0; nt < 4; nt++) {
            sacc[nt][0] = 0.f; sacc[nt][1] = 0.f;
            sacc[nt][2] = 0.f; sacc[nt][3] = 0.f;
        }
        #pragma unroll
        for (int ks = 0; ks < 16; ks++) {
            uint32_t bh4[2][4], bl4[2][4];
            ldsm4(bh4[0], Khs_u + (koff + ks * 8) * 4);
            ldsm4(bh4[1], Khs_u + (koff + 16 * 132 + ks * 8) * 4);
            ldsm4(bl4[0], Kls_u + (koff + ks * 8) * 4);
            ldsm4(bl4[1], Kls_u + (koff + 16 * 132 + ks * 8) * 4);
            #pragma unroll
            for (int nt = 0; nt < 4; nt++) {
                mma_tf32(sacc[nt], qf[ks], &bh4[nt >> 1][(nt & 1) * 2]);
                mma_tf32(sacc[nt], qf[ks], &bl4[nt >> 1][(nt & 1) * 2]);
            }
        }

        // ---- causal mask (only when tile can cross the diagonal for this warp)
        if (kt * 32 + 31 > qt * 128 + w * 16) {
            #pragma unroll
            for (int nt = 0; nt < 4; nt++) {
                int col = kt * 32 + nt * 8 + 2 * c;
                if (col     > rg0) sacc[nt][0] = -1e30f;
                if (col + 1 > rg0) sacc[nt][1] = -1e30f;
                if (col     > rg8) sacc[nt][2] = -1e30f;
                if (col + 1 > rg8) sacc[nt][3] = -1e30f;
            }
        }

        // ---- online softmax (rows g, g+8; reduce over quad lanes)
        float mx0 = -1e30f, mx1 = -1e30f;
        #pragma unroll
        for (int nt = 0; nt < 4; nt++) {
            mx0 = fmaxf(mx0, fmaxf(sacc[nt][0], sacc[nt][1]));
            mx1 = fmaxf(mx1, fmaxf(sacc[nt][2], sacc[nt][3]));
        }
        mx0 = fmaxf(mx0, __shfl_xor_sync(0xffffffffu, mx0, 1));
        mx0 = fmaxf(mx0, __shfl_xor_sync(0xffffffffu, mx0, 2));
        mx1 = fmaxf(mx1, __shfl_xor_sync(0xffffffffu, mx1, 1));
        mx1 = fmaxf(mx1, __shfl_xor_sync(0xffffffffu, mx1, 2));
        float nm0 = fmaxf(m0v, mx0), nm1 = fmaxf(m1v, mx1);
        float cf0 = expf_fast(m0v - nm0), cf1 = expf_fast(m1v - nm1);
        m0v = nm0; m1v = nm1;

        uint32_t pt[4][4];
        float rs0 = 0.f, rs1 = 0.f;
        #pragma unroll
        for (int nt = 0; nt < 4; nt++) {
            float p0 = expf_fast(sacc[nt][0] - nm0);
            float p1 = expf_fast(sacc[nt][1] - nm0);
            float p2 = expf_fast(sacc[nt][2] - nm1);
            float p3 = expf_fast(sacc[nt][3] - nm1);
            rs0 += p0 + p1; rs1 += p2 + p3;
            pt[nt][0] = f2tf(p0); pt[nt][1] = f2tf(p1);
            pt[nt][2] = f2tf(p2); pt[nt][3] = f2tf(p3);
        }
        rs0 += __shfl_xor_sync(0xffffffffu, rs0, 1);
        rs0 += __shfl_xor_sync(0xffffffffu, rs0, 2);
        rs1 += __shfl_xor_sync(0xffffffffu, rs1, 1);
        rs1 += __shfl_xor_sync(0xffffffffu, rs1, 2);
        l0 = l0 * cf0 + rs0;
        l1 = l1 * cf1 + rs1;

        #pragma unroll
        for (int nt2 = 0; nt2 < 16; nt2++) {
            oacc[nt2][0] *= cf0; oacc[nt2][1] *= cf0;
            oacc[nt2][2] *= cf1; oacc[nt2][3] *= cf1;
        }

        // ---- P acc-frag -> A-frag permutation via shfl, then O += P*V
        const int src  = (lane & 0x1C) | (c >> 1);
        const int src2 = src + 2;
        #pragma unroll
        for (int ks2 = 0; ks2 < 4; ks2++) {
            uint32_t e0 = __shfl_sync(0xffffffffu, pt[ks2][0], src);
            uint32_t e1 = __shfl_sync(0xffffffffu, pt[ks2][1], src);
            uint32_t e2 = __shfl_sync(0xffffffffu, pt[ks2][2], src);
            uint32_t e3 = __shfl_sync(0xffffffffu, pt[ks2][3], src);
            uint32_t f0 = __shfl_sync(0xffffffffu, pt[ks2][0], src2);
            uint32_t f1 = __shfl_sync(0xffffffffu, pt[ks2][1], src2);
            uint32_t f2x = __shfl_sync(0xffffffffu, pt[ks2][2], src2);
            uint32_t f3 = __shfl_sync(0xffffffffu, pt[ks2][3], src2);
            uint32_t af[4];
            af[0] = (c & 1) ? e1 : e0;
            af[1] = (c & 1) ? e3 : e2;
            af[2] = (c & 1) ? f1 : f0;
            af[3] = (c & 1) ? f3 : f2x;
            uint32_t vf[8][4];
            #pragma unroll
            for (int vg = 0; vg < 8; vg++)
                ldsm4(vf[vg], Vt_u + (voff + vg * 16 * 36 + ks2 * 8) * 4);
            #pragma unroll
            for (int nt2 = 0; nt2 < 16; nt2++)
                mma_tf32(oacc[nt2], af, &vf[nt2 >> 1][(nt2 & 1) * 2]);
        }

        // issue next KV stage AFTER compute (LDSMs first in the LSU queue)
        if (kt + 2 < nkt) kvissue(kt + 2);
        cp_commit();
    }

    // ---- epilogue: normalize, tf32-round (feeds proj GEMM), store
    float inv0 = 1.f / l0, inv1 = 1.f / l1;
    float* Yb = Y + ((size_t)b * T_ + (size_t)qt * 128) * C_ + h * HD_;
    const int lr0 = w * 16 + g;
    #pragma unroll
    for (int nt2 = 0; nt2 < 16; nt2++) {
        *(float2*)(Yb + (size_t)lr0 * C_ + nt2 * 8 + 2 * c) =
            make_float2(f2tf_f(oacc[nt2][0] * inv0), f2tf_f(oacc[nt2][1] * inv0));
        *(float2*)(Yb + (size_t)(lr0 + 8) * C_ + nt2 * 8 + 2 * c) =
            make_float2(f2tf_f(oacc[nt2][2] * inv1), f2tf_f(oacc[nt2][3] * inv1));
    }
}

// ---------------- launch --------------------------------------------------------
extern "C" void kernel_launch(void* const* d_in, const int* in_sizes, int n_in,
                              void* d_out, int out_size)
{
    const float* x     = (const float*)d_in[0];
    const float* rope  = (const float*)d_in[1];
    const float* Wqkv  = (const float*)d_in[2];
    const float* Wproj = (const float*)d_in[3];
    float* out = (float*)d_out;

    float *qkv, *q, *khi, *klo, *v, *vt, *y, *xtf, *wqkvT, *wprojT;
    cudaGetSymbolAddress((void**)&qkv,    g_qkv);
    cudaGetSymbolAddress((void**)&q,      g_q);
    cudaGetSymbolAddress((void**)&khi,    g_khi);
    cudaGetSymbolAddress((void**)&klo,    g_klo);
    cudaGetSymbolAddress((void**)&v,      g_v);
    cudaGetSymbolAddress((void**)&vt,     g_vt);
    cudaGetSymbolAddress((void**)&y,      g_y);
    cudaGetSymbolAddress((void**)&xtf,    g_xtf);
    cudaGetSymbolAddress((void**)&wqkvT,  g_wqkvT);
    cudaGetSymbolAddress((void**)&wprojT, g_wprojT);

    cudaFuncSetAttribute(gemm_tf32, cudaFuncAttributeMaxDynamicSharedMemorySize,
                         GSM_BYTES);
    cudaFuncSetAttribute(attn_tc, cudaFuncAttributeMaxDynamicSharedMemorySize,
                         ASM_BYTES);

    // 0) operand prep
    tf32_round_kernel<<<(B_ * T_ * C_ / 4) / 256, 256>>>(x, xtf);
    transpose_kernel<<<dim3((3 * C_) / 32, C_ / 32), 256>>>(Wqkv, wqkvT, C_, 3 * C_);
    transpose_kernel<<<dim3(C_ / 32, C_ / 32), 256>>>(Wproj, wprojT, C_, C_);

    // 1) qkv = x @ Wqkv
    gemm_tf32<<<dim3((B_ * T_) / 128, (3 * C_) / 256), 256, GSM_BYTES>>>(
        xtf, wqkvT, qkv, B_ * T_, 3 * C_, C_);

    // 2) RoPE + split-K + tf32 rounding, then V^T for PV ldmatrix
    rope_kernel<<<(B_ * T_ * H_ * (HD_ / 2)) / 256, 256>>>(qkv, rope, q, khi, klo, v);
    vtrans_kernel<<<dim3(T_ / 32, HD_ / 32, B_ * H_), 256>>>(v, vt);

    // 3) tensor-core causal flash attention -> y
    attn_tc<<<dim3(T_ / 128, B_ * H_), 256, ASM_BYTES>>>(q, khi, klo, vt, y);

    // 4) out = y @ Wproj
    gemm_tf32<<<dim3((B_ * T_) / 128, C_ / 256), 256, GSM_BYTES>>>(
        y, wprojT, out, B_ * T_, C_, C_);
}

// round 14
// speedup vs baseline: 1.5448x; 1.5448x over previous
#include <cuda_runtime.h>
#include <cstdint>
#include <cstddef>

#define B_  4
#define T_  2048
#define C_  2048
#define H_  16
#define HD_ 128

// ---------------- scratch (static __device__ — no allocations allowed) ----------
__device__ float g_qkv[(size_t)B_ * T_ * 3 * C_];          // [B*T, 3C]
__device__ float g_q  [(size_t)B_ * H_ * T_ * HD_];        // [B,H,T,HD] tf32, pre-scaled
__device__ float g_khi[(size_t)B_ * H_ * T_ * HD_];        // K hi (tf32)
__device__ float g_klo[(size_t)B_ * H_ * T_ * HD_];        // K lo (tf32 of residual)
__device__ float g_v  [(size_t)B_ * H_ * T_ * HD_];        // V (tf32-rounded)
__device__ float g_y[(size_t)B_ * T_ * C_];                // attention out (tf32-rounded)
__device__ float g_xtf[(size_t)B_ * T_ * C_];              // x rounded to tf32
__device__ float g_wqkvT[(size_t)3 * C_ * C_];             // Wqkv^T  [3C, C] (tf32)
__device__ float g_wprojT[(size_t)C_ * C_];                // Wproj^T [C, C] (tf32)

// ---------------- small helpers -------------------------------------------------
__device__ __forceinline__ uint32_t f2tf(float x) {
    uint32_t u;
    asm("cvt.rna.tf32.f32 %0, %1;" : "=r"(u) : "f"(x));
    return u;
}
__device__ __forceinline__ float f2tf_f(float x) { return __uint_as_float(f2tf(x)); }

__device__ __forceinline__ void mma_tf32(float* d, const uint32_t* a,
                                         const uint32_t* b) {
    asm volatile(
        "mma.sync.aligned.m16n8k8.row.col.f32.tf32.tf32.f32 "
        "{%0,%1,%2,%3}, {%4,%5,%6,%7}, {%8,%9}, {%0,%1,%2,%3};"
        : "+f"(d[0]), "+f"(d[1]), "+f"(d[2]), "+f"(d[3])
        : "r"(a[0]), "r"(a[1]), "r"(a[2]), "r"(a[3]), "r"(b[0]), "r"(b[1]));
}
__device__ __forceinline__ uint32_t smem_u32(const void* p) {
    uint32_t a;
    asm("{ .reg .u64 t; cvta.to.shared.u64 t, %1; cvt.u32.u64 %0, t; }"
        : "=r"(a) : "l"(p));
    return a;
}
// ldmatrix x4: loads four 8x4-f32 blocks; per-lane addr = row of matrix (lane/8)
__device__ __forceinline__ void ldsm4(uint32_t* r, uint32_t addr) {
    asm volatile("ldmatrix.sync.aligned.m8n8.x4.shared.b16 {%0,%1,%2,%3}, [%4];"
                 : "=r"(r[0]), "=r"(r[1]), "=r"(r[2]), "=r"(r[3]) : "r"(addr));
}
__device__ __forceinline__ void cp16(uint32_t dst, const void* src) {
    asm volatile("cp.async.cg.shared.global [%0], [%1], 16;"
                 :: "r"(dst), "l"(src) : "memory");
}
__device__ __forceinline__ void cp_commit() {
    asm volatile("cp.async.commit_group;" ::: "memory");
}
template <int N>
__device__ __forceinline__ void cp_wait() {
    asm volatile("cp.async.wait_group %0;" :: "n"(N) : "memory");
}
// FFMA-pipe exp (keeps MUFU free; poly rel err ~2e-6)
__device__ __forceinline__ float expf_fast(float x) {
    float y = fmaxf(x, -60.f) * 1.4426950408889634f;
    float nf;
    asm("cvt.rni.f32.f32 %0, %1;" : "=f"(nf) : "f"(y));
    float f = y - nf;
    float p =              1.3333558e-3f;
    p = fmaf(p, f, 9.6181291e-3f);
    p = fmaf(p, f, 5.5504109e-2f);
    p = fmaf(p, f, 2.4022651e-1f);
    p = fmaf(p, f, 6.9314718e-1f);
    p = fmaf(p, f, 1.0f);
    return __int_as_float(__float_as_int(p) + (((int)nf) << 23));
}

// ===================== TF32 mma.sync GEMM (cp.async 4-stage + ldmatrix) =========
// 512 threads = 16 warps (4 M x 4 N), warp tile 32x64 — doubles warps/SMSP vs
// round 10 to cover LDSM/LDGSTS latency. Copies issued AFTER compute (LSU order).
#define APITCH 20
#define ABUF_FLOATS (128 * APITCH)
#define BBUF_FLOATS (256 * APITCH)
#define BUF_FLOATS  (ABUF_FLOATS + BBUF_FLOATS)
#define STAGES 4
#define GSM_BYTES (STAGES * BUF_FLOATS * 4)

__global__ __launch_bounds__(512, 1) void gemm_tf32(
    const float* __restrict__ A, const float* __restrict__ Bt,
    float* __restrict__ Cm, int M, int N, int K)
{
    extern __shared__ float sm[];
    const uint32_t sbase = smem_u32(sm);
    const int tid  = threadIdx.x;
    const int wid  = tid >> 5;
    const int lane = tid & 31;
    const int g    = lane >> 2;
    const int c    = lane & 3;
    const int warp_m = wid & 3;      // 4 M groups x 32 rows
    const int warp_n = wid >> 2;     // 4 N groups x 64 cols

    const size_t m0 = (size_t)blockIdx.x * 128;
    const size_t n0 = (size_t)blockIdx.y * 256;

    const int aoff = (warp_m * 32 + (lane & 7) + ((lane >> 3) & 1) * 8) * APITCH
                   + ((lane >> 4) & 1) * 4;
    const int boff = (warp_n * 64 + (lane & 7) + ((lane >> 4) & 1) * 8) * APITCH
                   + ((lane >> 3) & 1) * 4;

    // per-thread copy coords: A 512 float4 (1/thread), B 1024 float4 (2/thread)
    const int ar  = tid >> 2;
    const int akk = (tid & 3) << 2;
    int br[2], bkk[2];
    #pragma unroll
    for (int j = 0; j < 2; j++) {
        br[j]  = (tid + j * 512) >> 2;
        bkk[j] = ((tid + j * 512) & 3) << 2;
    }

    float acc[2][8][4];
    #pragma unroll
    for (int mi = 0; mi < 2; mi++)
        #pragma unroll
        for (int ni = 0; ni < 8; ni++)
            #pragma unroll
            for (int q = 0; q < 4; q++) acc[mi][ni][q] = 0.f;

    const int niter = K >> 4;

    auto issue = [&](int it) {
        const int k0 = it << 4;
        const uint32_t As = sbase + (uint32_t)(it & (STAGES - 1)) * (BUF_FLOATS * 4);
        const uint32_t Bs = As + ABUF_FLOATS * 4;
        cp16(As + (ar * APITCH + akk) * 4, A + (m0 + ar) * K + k0 + akk);
        #pragma unroll
        for (int j = 0; j < 2; j++)
            cp16(Bs + (br[j] * APITCH + bkk[j]) * 4,
                 Bt + (n0 + br[j]) * K + k0 + bkk[j]);
    };

    #pragma unroll
    for (int s = 0; s < STAGES - 1; s++) {
        if (s < niter) issue(s);
        cp_commit();
    }

    for (int it = 0; it < niter; ++it) {
        cp_wait<STAGES - 2>();
        __syncthreads();

        const uint32_t As_u = sbase + (uint32_t)(it & (STAGES - 1)) * (BUF_FLOATS * 4);
        const uint32_t Bs_u = As_u + ABUF_FLOATS * 4;
        #pragma unroll
        for (int ks = 0; ks < 2; ks++) {
            uint32_t af[2][4], bf[4][4];
            #pragma unroll
            for (int mi = 0; mi < 2; mi++)
                ldsm4(af[mi], As_u + (aoff + mi * 16 * APITCH + ks * 8) * 4);
            #pragma unroll
            for (int np = 0; np < 4; np++)
                ldsm4(bf[np], Bs_u + (boff + np * 16 * APITCH + ks * 8) * 4);
            #pragma unroll
            for (int mi = 0; mi < 2; mi++)
                #pragma unroll
                for (int ni = 0; ni < 8; ni++)
                    mma_tf32(acc[mi][ni], af[mi], &bf[ni >> 1][(ni & 1) * 2]);
        }

        // issue next stage AFTER compute (LDSMs first in the LSU queue)
        if (it + STAGES - 1 < niter) issue(it + STAGES - 1);
        cp_commit();
    }

    #pragma unroll
    for (int mi = 0; mi < 2; mi++) {
        const size_t row0 = m0 + warp_m * 32 + mi * 16 + g;
        #pragma unroll
        for (int ni = 0; ni < 8; ni++) {
            const size_t col = n0 + warp_n * 64 + ni * 8 + 2 * c;
            *(float2*)(Cm + row0 * N + col) =
                make_float2(acc[mi][ni][0], acc[mi][ni][1]);
            *(float2*)(Cm + (row0 + 8) * N + col) =
                make_float2(acc[mi][ni][2], acc[mi][ni][3]);
        }
    }
}

// ---------------- tf32 pre-round ------------------------------------------------
__global__ __launch_bounds__(256) void tf32_round_kernel(
    const float* __restrict__ in, float* __restrict__ out)
{
    int i = blockIdx.x * 256 + threadIdx.x;
    float4 v = ((const float4*)in)[i];
    v.x = f2tf_f(v.x); v.y = f2tf_f(v.y);
    v.z = f2tf_f(v.z); v.w = f2tf_f(v.w);
    ((float4*)out)[i] = v;
}

// ---------------- transpose + tf32 round ---------------------------------------
__global__ __launch_bounds__(256) void transpose_kernel(
    const float* __restrict__ in, float* __restrict__ out, int R, int Cc)
{
    __shared__ float tile[32][33];
    int c0 = blockIdx.x * 32, r0 = blockIdx.y * 32;
    int tx = threadIdx.x & 31, ty = threadIdx.x >> 5;
    #pragma unroll
    for (int j = 0; j < 4; j++)
        tile[ty + j * 8][tx] = in[(size_t)(r0 + ty + j * 8) * Cc + c0 + tx];
    __syncthreads();
    #pragma unroll
    for (int j = 0; j < 4; j++)
        out[(size_t)(c0 + ty + j * 8) * R + r0 + tx] = f2tf_f(tile[tx][ty + j * 8]);
}

// ---------------- RoPE: qkv -> q(scaled,tf32), khi, klo, v(tf32) ----------------
__global__ __launch_bounds__(256) void rope_kernel(
    const float* __restrict__ qkv, const float* __restrict__ rope,
    float* __restrict__ q, float* __restrict__ khi,
    float* __restrict__ klo, float* __restrict__ v)
{
    int idx = blockIdx.x * 256 + threadIdx.x;
    int p = idx & 63;
    int h = (idx >> 6) & 15;
    int t = (idx >> 10) & 2047;
    int b = idx >> 21;
    const float scale = 0.08838834764831845f;   // 1/sqrt(128)

    float2 cs = ((const float2*)rope)[t * 64 + p];
    size_t base_in = ((size_t)(b * T_ + t)) * (3 * C_) + h * HD_ + p * 2;
    float2 qv = *(const float2*)(qkv + base_in);
    float2 kv = *(const float2*)(qkv + base_in + C_);
    float2 vv = *(const float2*)(qkv + base_in + 2 * C_);

    float2 qo = make_float2((qv.x * cs.x - qv.y * cs.y) * scale,
                            (qv.y * cs.x + qv.x * cs.y) * scale);
    float2 ko = make_float2(kv.x * cs.x - kv.y * cs.y, kv.y * cs.x + kv.x * cs.y);

    float2 qr  = make_float2(f2tf_f(qo.x), f2tf_f(qo.y));
    float2 khv = make_float2(f2tf_f(ko.x), f2tf_f(ko.y));
    float2 klv = make_float2(f2tf_f(ko.x - khv.x), f2tf_f(ko.y - khv.y));
    float2 vr  = make_float2(f2tf_f(vv.x), f2tf_f(vv.y));

    size_t base_out = ((size_t)((b * H_ + h) * T_ + t)) * HD_ + p * 2;
    *(float2*)(q   + base_out) = qr;
    *(float2*)(khi + base_out) = khv;
    *(float2*)(klo + base_out) = klv;
    *(float2*)(v   + base_out) = vr;
}

// ================== Tensor-core flash attention (tf32, causal) ==================
// EXACT round-10 configuration (best known: 2563us): K frags via ldmatrix,
// V via scalar LDS (interleaves with MMAs), kvissue after compute.
#define KV_TILE_F   (32 * 132)                  // 4224 floats
#define KV_STRIDE_F (3 * KV_TILE_F)             // 12672 floats per stage
#define ASM_BYTES   (3 * KV_STRIDE_F * 4)       // 152064 bytes

__global__ __launch_bounds__(256, 1) void attn_tc(
    const float* __restrict__ Qg, const float* __restrict__ Khig,
    const float* __restrict__ Klog, const float* __restrict__ Vg,
    float* __restrict__ Y)
{
    extern __shared__ float smn[];
    const uint32_t sbase = smem_u32(smn);
    const int qt = (int)gridDim.x - 1 - (int)blockIdx.x;   // heavy tiles first
    const int bh = blockIdx.y;
    const int b = bh >> 4, h = bh & 15;
    const int tid = threadIdx.x;
    const int w = tid >> 5, lane = tid & 31, g = lane >> 2, c = lane & 3;
    const size_t head = (size_t)bh * T_ * HD_;

    const int koff = ((lane & 7) + ((lane >> 4) & 1) * 8) * 132
                   + ((lane >> 3) & 1) * 4;

    // ---- stage Q tile (already tf32+scaled) into smem pitch 132, extract frags
    {
        const float4* Qt = (const float4*)(Qg + head + (size_t)qt * 128 * HD_);
        for (int i = tid; i < 128 * 32; i += 256) {
            int r = i >> 5, d4 = (i & 31) << 2;
            float4 qv = Qt[i];
            float* dst = smn + r * 132 + d4;
            dst[0] = qv.x; dst[1] = qv.y; dst[2] = qv.z; dst[3] = qv.w;
        }
    }
    __syncthreads();
    uint32_t qf[16][4];
    {
        const float* q0 = smn + (w * 16 + g) * 132 + c;
        #pragma unroll
        for (int ks = 0; ks < 16; ks++) {
            qf[ks][0] = __float_as_uint(q0[ks * 8]);
            qf[ks][1] = __float_as_uint(q0[ks * 8 + 8 * 132]);
            qf[ks][2] = __float_as_uint(q0[ks * 8 + 4]);
            qf[ks][3] = __float_as_uint(q0[ks * 8 + 8 * 132 + 4]);
        }
    }
    __syncthreads();

    float oacc[16][4];
    #pragma unroll
    for (int i = 0; i < 16; i++) {
        oacc[i][0] = 0.f; oacc[i][1] = 0.f; oacc[i][2] = 0.f; oacc[i][3] = 0.f;
    }
    float m0v = -1e30f, m1v = -1e30f, l0 = 0.f, l1 = 0.f;

    const int nkt = qt * 4 + 4;
    const int cr = tid >> 3;              // copy row 0..31
    const int cc = (tid & 7) << 2;        // copy col base (floats)

    auto kvissue = [&](int kt) {
        uint32_t dstb = sbase + (uint32_t)(kt % 3) * (KV_STRIDE_F * 4)
                      + cr * (132 * 4);
        size_t srcb = head + ((size_t)kt * 32 + cr) * HD_;
        #pragma unroll
        for (int ch = 0; ch < 4; ch++) {
            uint32_t dst = dstb + (cc + ch * 32) * 4;
            size_t src = srcb + cc + ch * 32;
            cp16(dst,                     Khig + src);
            cp16(dst + KV_TILE_F * 4,     Klog + src);
            cp16(dst + 2 * KV_TILE_F * 4, Vg + src);
        }
    };
    kvissue(0); cp_commit();
    if (nkt > 1) kvissue(1);
    cp_commit();

    const int rg0 = qt * 128 + w * 16 + g;
    const int rg8 = rg0 + 8;

    for (int kt = 0; kt < nkt; kt++) {
        cp_wait<1>();
        __syncthreads();
        const uint32_t Khs_u = sbase + (uint32_t)(kt % 3) * (KV_STRIDE_F * 4);
        const uint32_t Kls_u = Khs_u + KV_TILE_F * 4;
        const float* Vs = smn + (kt % 3) * KV_STRIDE_F + 2 * KV_TILE_F;

        // ---- S = Q*Khi + Q*Klo  (16x32 per warp), K frags via ldmatrix
        float sacc[4][4];
        #pragma unroll
        for (int nt = 0; nt < 4; nt++) {
            sacc[nt][0] = 0.f; sacc[nt][1] = 0.f;
            sacc[nt][2] = 0.f; sacc[nt][3] = 0.f;
        }
        #pragma unroll
        for (int ks = 0; ks < 16; ks++) {
            uint32_t bh4[2][4], bl4[2][4];
            ldsm4(bh4[0], Khs_u + (koff + ks * 8) * 4);
            ldsm4(bh4[1], Khs_u + (koff + 16 * 132 + ks * 8) * 4);
            ldsm4(bl4[0], Kls_u + (koff + ks * 8) * 4);
            ldsm4(bl4[1], Kls_u + (koff + 16 * 132 + ks * 8) * 4);
            #pragma unroll
            for (int nt = 0; nt < 4; nt++) {
                mma_tf32(sacc[nt], qf[ks], &bh4[nt >> 1][(nt & 1) * 2]);
                mma_tf32(sacc[nt], qf[ks], &bl4[nt >> 1][(nt & 1) * 2]);
            }
        }

        // ---- causal mask (only when tile can cross the diagonal for this warp)
        if (kt * 32 + 31 > qt * 128 + w * 16) {
            #pragma unroll
            for (int nt = 0; nt < 4; nt++) {
                int col = kt * 32 + nt * 8 + 2 * c;
                if (col     > rg0) sacc[nt][0] = -1e30f;
                if (col + 1 > rg0) sacc[nt][1] = -1e30f;
                if (col     > rg8) sacc[nt][2] = -1e30f;
                if (col + 1 > rg8) sacc[nt][3] = -1e30f;
            }
        }

        // ---- online softmax (rows g, g+8; reduce over quad lanes)
        float mx0 = -1e30f, mx1 = -1e30f;
        #pragma unroll
        for (int nt = 0; nt < 4; nt++) {
            mx0 = fmaxf(mx0, fmaxf(sacc[nt][0], sacc[nt][1]));
            mx1 = fmaxf(mx1, fmaxf(sacc[nt][2], sacc[nt][3]));
        }
        mx0 = fmaxf(mx0, __shfl_xor_sync(0xffffffffu, mx0, 1));
        mx0 = fmaxf(mx0, __shfl_xor_sync(0xffffffffu, mx0, 2));
        mx1 = fmaxf(mx1, __shfl_xor_sync(0xffffffffu, mx1, 1));
        mx1 = fmaxf(mx1, __shfl_xor_sync(0xffffffffu, mx1, 2));
        float nm0 = fmaxf(m0v, mx0), nm1 = fmaxf(m1v, mx1);
        float cf0 = expf_fast(m0v - nm0), cf1 = expf_fast(m1v - nm1);
        m0v = nm0; m1v = nm1;

        uint32_t pt[4][4];
        float rs0 = 0.f, rs1 = 0.f;
        #pragma unroll
        for (int nt = 0; nt < 4; nt++) {
            float p0 = expf_fast(sacc[nt][0] - nm0);
            float p1 = expf_fast(sacc[nt][1] - nm0);
            float p2 = expf_fast(sacc[nt][2] - nm1);
            float p3 = expf_fast(sacc[nt][3] - nm1);
            rs0 += p0 + p1; rs1 += p2 + p3;
            pt[nt][0] = f2tf(p0); pt[nt][1] = f2tf(p1);
            pt[nt][2] = f2tf(p2); pt[nt][3] = f2tf(p3);
        }
        rs0 += __shfl_xor_sync(0xffffffffu, rs0, 1);
        rs0 += __shfl_xor_sync(0xffffffffu, rs0, 2);
        rs1 += __shfl_xor_sync(0xffffffffu, rs1, 1);
        rs1 += __shfl_xor_sync(0xffffffffu, rs1, 2);
        l0 = l0 * cf0 + rs0;
        l1 = l1 * cf1 + rs1;

        #pragma unroll
        for (int nt2 = 0; nt2 < 16; nt2++) {
            oacc[nt2][0] *= cf0; oacc[nt2][1] *= cf0;
            oacc[nt2][2] *= cf1; oacc[nt2][3] *= cf1;
        }

        // ---- P acc-frag -> A-frag permutation via shfl, then O += P*V
        const int src  = (lane & 0x1C) | (c >> 1);
        const int src2 = src + 2;
        #pragma unroll
        for (int ks2 = 0; ks2 < 4; ks2++) {
            uint32_t e0 = __shfl_sync(0xffffffffu, pt[ks2][0], src);
            uint32_t e1 = __shfl_sync(0xffffffffu, pt[ks2][1], src);
            uint32_t e2 = __shfl_sync(0xffffffffu, pt[ks2][2], src);
            uint32_t e3 = __shfl_sync(0xffffffffu, pt[ks2][3], src);
            uint32_t f0 = __shfl_sync(0xffffffffu, pt[ks2][0], src2);
            uint32_t f1 = __shfl_sync(0xffffffffu, pt[ks2][1], src2);
            uint32_t f2x = __shfl_sync(0xffffffffu, pt[ks2][2], src2);
            uint32_t f3 = __shfl_sync(0xffffffffu, pt[ks2][3], src2);
            uint32_t af[4];
            af[0] = (c & 1) ? e1 : e0;
            af[1] = (c & 1) ? e3 : e2;
            af[2] = (c & 1) ? f1 : f0;
            af[3] = (c & 1) ? f3 : f2x;
            #pragma unroll
            for (int nt2 = 0; nt2 < 16; nt2++) {
                const float* vp = Vs + (ks2 * 8 + c) * 132 + nt2 * 8 + g;
                uint32_t bf[2] = { __float_as_uint(vp[0]),
                                   __float_as_uint(vp[4 * 132]) };
                mma_tf32(oacc[nt2], af, bf);
            }
        }

        // issue next KV stage AFTER compute
        if (kt + 2 < nkt) kvissue(kt + 2);
        cp_commit();
    }

    // ---- epilogue: normalize, tf32-round (feeds proj GEMM), store
    float inv0 = 1.f / l0, inv1 = 1.f / l1;
    float* Yb = Y + ((size_t)b * T_ + (size_t)qt * 128) * C_ + h * HD_;
    const int lr0 = w * 16 + g;
    #pragma unroll
    for (int nt2 = 0; nt2 < 16; nt2++) {
        *(float2*)(Yb + (size_t)lr0 * C_ + nt2 * 8 + 2 * c) =
            make_float2(f2tf_f(oacc[nt2][0] * inv0), f2tf_f(oacc[nt2][1] * inv0));
        *(float2*)(Yb + (size_t)(lr0 + 8) * C_ + nt2 * 8 + 2 * c) =
            make_float2(f2tf_f(oacc[nt2][2] * inv1), f2tf_f(oacc[nt2][3] * inv1));
    }
}

// ---------------- launch --------------------------------------------------------
extern "C" void kernel_launch(void* const* d_in, const int* in_sizes, int n_in,
                              void* d_out, int out_size)
{
    const float* x     = (const float*)d_in[0];
    const float* rope  = (const float*)d_in[1];
    const float* Wqkv  = (const float*)d_in[2];
    const float* Wproj = (const float*)d_in[3];
    float* out = (float*)d_out;

    float *qkv, *q, *khi, *klo, *v, *y, *xtf, *wqkvT, *wprojT;
    cudaGetSymbolAddress((void**)&qkv,    g_qkv);
    cudaGetSymbolAddress((void**)&q,      g_q);
    cudaGetSymbolAddress((void**)&khi,    g_khi);
    cudaGetSymbolAddress((void**)&klo,    g_klo);
    cudaGetSymbolAddress((void**)&v,      g_v);
    cudaGetSymbolAddress((void**)&y,      g_y);
    cudaGetSymbolAddress((void**)&xtf,    g_xtf);
    cudaGetSymbolAddress((void**)&wqkvT,  g_wqkvT);
    cudaGetSymbolAddress((void**)&wprojT, g_wprojT);

    cudaFuncSetAttribute(gemm_tf32, cudaFuncAttributeMaxDynamicSharedMemorySize,
                         GSM_BYTES);
    cudaFuncSetAttribute(attn_tc, cudaFuncAttributeMaxDynamicSharedMemorySize,
                         ASM_BYTES);

    // 0) operand prep
    tf32_round_kernel<<<(B_ * T_ * C_ / 4) / 256, 256>>>(x, xtf);
    transpose_kernel<<<dim3((3 * C_) / 32, C_ / 32), 256>>>(Wqkv, wqkvT, C_, 3 * C_);
    transpose_kernel<<<dim3(C_ / 32, C_ / 32), 256>>>(Wproj, wprojT, C_, C_);

    // 1) qkv = x @ Wqkv
    gemm_tf32<<<dim3((B_ * T_) / 128, (3 * C_) / 256), 512, GSM_BYTES>>>(
        xtf, wqkvT, qkv, B_ * T_, 3 * C_, C_);

    // 2) RoPE + split-K + tf32 rounding
    rope_kernel<<<(B_ * T_ * H_ * (HD_ / 2)) / 256, 256>>>(qkv, rope, q, khi, klo, v);

    // 3) tensor-core causal flash attention -> y
    attn_tc<<<dim3(T_ / 128, B_ * H_), 256, ASM_BYTES>>>(q, khi, klo, v, y);

    // 4) out = y @ Wproj
    gemm_tf32<<<dim3((B_ * T_) / 128, C_ / 256), 512, GSM_BYTES>>>(
        y, wprojT, out, B_ * T_, C_, C_);
}

// round 16
// speedup vs baseline: 1.5882x; 1.0281x over previous
#include <cuda_runtime.h>
#include <cstdint>
#include <cstddef>

#define B_  4
#define T_  2048
#define C_  2048
#define H_  16
#define HD_ 128

// ---------------- scratch (static __device__ — no allocations allowed) ----------
__device__ float g_qkv[(size_t)B_ * T_ * 3 * C_];          // [B*T, 3C]
__device__ float g_q  [(size_t)B_ * H_ * T_ * HD_];        // [B,H,T,HD] tf32, pre-scaled
__device__ float g_khi[(size_t)B_ * H_ * T_ * HD_];        // K hi (tf32)
__device__ float g_klo[(size_t)B_ * H_ * T_ * HD_];        // K lo (tf32 of residual)
__device__ float g_v  [(size_t)B_ * H_ * T_ * HD_];        // V (tf32-rounded)
__device__ float g_y[(size_t)B_ * T_ * C_];                // attention out (tf32-rounded)
__device__ float g_xtf[(size_t)B_ * T_ * C_];              // x rounded to tf32
__device__ float g_wqkvT[(size_t)3 * C_ * C_];             // Wqkv^T  [3C, C] (tf32)
__device__ float g_wprojT[(size_t)C_ * C_];                // Wproj^T [C, C] (tf32)

// ---------------- small helpers -------------------------------------------------
__device__ __forceinline__ uint32_t f2tf(float x) {
    uint32_t u;
    asm("cvt.rna.tf32.f32 %0, %1;" : "=r"(u) : "f"(x));
    return u;
}
__device__ __forceinline__ float f2tf_f(float x) { return __uint_as_float(f2tf(x)); }

__device__ __forceinline__ void mma_tf32(float* d, const uint32_t* a,
                                         const uint32_t* b) {
    asm volatile(
        "mma.sync.aligned.m16n8k8.row.col.f32.tf32.tf32.f32 "
        "{%0,%1,%2,%3}, {%4,%5,%6,%7}, {%8,%9}, {%0,%1,%2,%3};"
        : "+f"(d[0]), "+f"(d[1]), "+f"(d[2]), "+f"(d[3])
        : "r"(a[0]), "r"(a[1]), "r"(a[2]), "r"(a[3]), "r"(b[0]), "r"(b[1]));
}
__device__ __forceinline__ uint32_t smem_u32(const void* p) {
    uint32_t a;
    asm("{ .reg .u64 t; cvta.to.shared.u64 t, %1; cvt.u32.u64 %0, t; }"
        : "=r"(a) : "l"(p));
    return a;
}
// ldmatrix x4: loads four 8x4-f32 blocks; per-lane addr = row of matrix (lane/8)
__device__ __forceinline__ void ldsm4(uint32_t* r, uint32_t addr) {
    asm volatile("ldmatrix.sync.aligned.m8n8.x4.shared.b16 {%0,%1,%2,%3}, [%4];"
                 : "=r"(r[0]), "=r"(r[1]), "=r"(r[2]), "=r"(r[3]) : "r"(addr));
}
__device__ __forceinline__ void cp16(uint32_t dst, const void* src) {
    asm volatile("cp.async.cg.shared.global [%0], [%1], 16;"
                 :: "r"(dst), "l"(src) : "memory");
}
__device__ __forceinline__ void cp_commit() {
    asm volatile("cp.async.commit_group;" ::: "memory");
}
template <int N>
__device__ __forceinline__ void cp_wait() {
    asm volatile("cp.async.wait_group %0;" :: "n"(N) : "memory");
}
// FFMA-pipe exp (keeps MUFU free; poly rel err ~2e-6)
__device__ __forceinline__ float expf_fast(float x) {
    float y = fmaxf(x, -60.f) * 1.4426950408889634f;
    float nf;
    asm("cvt.rni.f32.f32 %0, %1;" : "=f"(nf) : "f"(y));
    float f = y - nf;
    float p =              1.3333558e-3f;
    p = fmaf(p, f, 9.6181291e-3f);
    p = fmaf(p, f, 5.5504109e-2f);
    p = fmaf(p, f, 2.4022651e-1f);
    p = fmaf(p, f, 6.9314718e-1f);
    p = fmaf(p, f, 1.0f);
    return __int_as_float(__float_as_int(p) + (((int)nf) << 23));
}

// ===================== TF32 mma.sync GEMM ======================================
// 512 threads = 16 warps (4 M x 4 N), warp tile 32x64.
// 6-slot BK=16 smem ring, TWO stages computed per barrier (64 MMAs/warp/sync):
// halves barrier + cp_wait frequency vs round 14. Slots refilled (it+4, it+5)
// map to stages it-2 / it-1, last read in iteration it-2 => fenced by this
// iteration's barrier. Copies issued AFTER compute (LSU-order lesson, R11/12).
#define APITCH 20
#define ABUF_FLOATS (128 * APITCH)
#define BBUF_FLOATS (256 * APITCH)
#define BUF_FLOATS  (ABUF_FLOATS + BBUF_FLOATS)
#define NSLOTS 6
#define GSM_BYTES (NSLOTS * BUF_FLOATS * 4)     // 184320

__global__ __launch_bounds__(512, 1) void gemm_tf32(
    const float* __restrict__ A, const float* __restrict__ Bt,
    float* __restrict__ Cm, int M, int N, int K)
{
    extern __shared__ float sm[];
    const uint32_t sbase = smem_u32(sm);
    const int tid  = threadIdx.x;
    const int wid  = tid >> 5;
    const int lane = tid & 31;
    const int g    = lane >> 2;
    const int c    = lane & 3;
    const int warp_m = wid & 3;      // 4 M groups x 32 rows
    const int warp_n = wid >> 2;     // 4 N groups x 64 cols

    const size_t m0 = (size_t)blockIdx.x * 128;
    const size_t n0 = (size_t)blockIdx.y * 256;

    const int aoff = (warp_m * 32 + (lane & 7) + ((lane >> 3) & 1) * 8) * APITCH
                   + ((lane >> 4) & 1) * 4;
    const int boff = (warp_n * 64 + (lane & 7) + ((lane >> 4) & 1) * 8) * APITCH
                   + ((lane >> 3) & 1) * 4;

    // per-thread copy coords: A 512 float4 (1/thread), B 1024 float4 (2/thread)
    const int ar  = tid >> 2;
    const int akk = (tid & 3) << 2;
    int br[2], bkk[2];
    #pragma unroll
    for (int j = 0; j < 2; j++) {
        br[j]  = (tid + j * 512) >> 2;
        bkk[j] = ((tid + j * 512) & 3) << 2;
    }

    float acc[2][8][4];
    #pragma unroll
    for (int mi = 0; mi < 2; mi++)
        #pragma unroll
        for (int ni = 0; ni < 8; ni++)
            #pragma unroll
            for (int q = 0; q < 4; q++) acc[mi][ni][q] = 0.f;

    const int niter = K >> 4;   // 128 (even)

    auto issue = [&](int it) {
        const int k0 = it << 4;
        const uint32_t As = sbase + (uint32_t)(it % NSLOTS) * (BUF_FLOATS * 4);
        const uint32_t Bs = As + ABUF_FLOATS * 4;
        cp16(As + (ar * APITCH + akk) * 4, A + (m0 + ar) * K + k0 + akk);
        #pragma unroll
        for (int j = 0; j < 2; j++)
            cp16(Bs + (br[j] * APITCH + bkk[j]) * 4,
                 Bt + (n0 + br[j]) * K + k0 + bkk[j]);
    };

    auto compute = [&](int slot) {
        const uint32_t As_u = sbase + (uint32_t)slot * (BUF_FLOATS * 4);
        const uint32_t Bs_u = As_u + ABUF_FLOATS * 4;
        #pragma unroll
        for (int ks = 0; ks < 2; ks++) {
            uint32_t af[2][4], bf[4][4];
            #pragma unroll
            for (int mi = 0; mi < 2; mi++)
                ldsm4(af[mi], As_u + (aoff + mi * 16 * APITCH + ks * 8) * 4);
            #pragma unroll
            for (int np = 0; np < 4; np++)
                ldsm4(bf[np], Bs_u + (boff + np * 16 * APITCH + ks * 8) * 4);
            #pragma unroll
            for (int mi = 0; mi < 2; mi++)
                #pragma unroll
                for (int ni = 0; ni < 8; ni++)
                    mma_tf32(acc[mi][ni], af[mi], &bf[ni >> 1][(ni & 1) * 2]);
        }
    };

    // prologue: stages 0..3, one group each
    #pragma unroll
    for (int s = 0; s < 4; s++) {
        if (s < niter) issue(s);
        cp_commit();
    }

    for (int it = 0; it < niter; it += 2) {
        cp_wait<2>();          // stages it, it+1 complete
        __syncthreads();

        compute(it % NSLOTS);
        compute((it + 1) % NSLOTS);

        // refill AFTER compute (LDSMs first in LSU queue); separate groups so
        // the next wait<2> guarantees stage it+3.
        if (it + 4 < niter) issue(it + 4);
        cp_commit();
        if (it + 5 < niter) issue(it + 5);
        cp_commit();
    }

    #pragma unroll
    for (int mi = 0; mi < 2; mi++) {
        const size_t row0 = m0 + warp_m * 32 + mi * 16 + g;
        #pragma unroll
        for (int ni = 0; ni < 8; ni++) {
            const size_t col = n0 + warp_n * 64 + ni * 8 + 2 * c;
            *(float2*)(Cm + row0 * N + col) =
                make_float2(acc[mi][ni][0], acc[mi][ni][1]);
            *(float2*)(Cm + (row0 + 8) * N + col) =
                make_float2(acc[mi][ni][2], acc[mi][ni][3]);
        }
    }
}

// ---------------- tf32 pre-round ------------------------------------------------
__global__ __launch_bounds__(256) void tf32_round_kernel(
    const float* __restrict__ in, float* __restrict__ out)
{
    int i = blockIdx.x * 256 + threadIdx.x;
    float4 v = ((const float4*)in)[i];
    v.x = f2tf_f(v.x); v.y = f2tf_f(v.y);
    v.z = f2tf_f(v.z); v.w = f2tf_f(v.w);
    ((float4*)out)[i] = v;
}

// ---------------- transpose + tf32 round ---------------------------------------
__global__ __launch_bounds__(256) void transpose_kernel(
    const float* __restrict__ in, float* __restrict__ out, int R, int Cc)
{
    __shared__ float tile[32][33];
    int c0 = blockIdx.x * 32, r0 = blockIdx.y * 32;
    int tx = threadIdx.x & 31, ty = threadIdx.x >> 5;
    #pragma unroll
    for (int j = 0; j < 4; j++)
        tile[ty + j * 8][tx] = in[(size_t)(r0 + ty + j * 8) * Cc + c0 + tx];
    __syncthreads();
    #pragma unroll
    for (int j = 0; j < 4; j++)
        out[(size_t)(c0 + ty + j * 8) * R + r0 + tx] = f2tf_f(tile[tx][ty + j * 8]);
}

// ---------------- RoPE: qkv -> q(scaled,tf32), khi, klo, v(tf32) ----------------
__global__ __launch_bounds__(256) void rope_kernel(
    const float* __restrict__ qkv, const float* __restrict__ rope,
    float* __restrict__ q, float* __restrict__ khi,
    float* __restrict__ klo, float* __restrict__ v)
{
    int idx = blockIdx.x * 256 + threadIdx.x;
    int p = idx & 63;
    int h = (idx >> 6) & 15;
    int t = (idx >> 10) & 2047;
    int b = idx >> 21;
    const float scale = 0.08838834764831845f;   // 1/sqrt(128)

    float2 cs = ((const float2*)rope)[t * 64 + p];
    size_t base_in = ((size_t)(b * T_ + t)) * (3 * C_) + h * HD_ + p * 2;
    float2 qv = *(const float2*)(qkv + base_in);
    float2 kv = *(const float2*)(qkv + base_in + C_);
    float2 vv = *(const float2*)(qkv + base_in + 2 * C_);

    float2 qo = make_float2((qv.x * cs.x - qv.y * cs.y) * scale,
                            (qv.y * cs.x + qv.x * cs.y) * scale);
    float2 ko = make_float2(kv.x * cs.x - kv.y * cs.y, kv.y * cs.x + kv.x * cs.y);

    float2 qr  = make_float2(f2tf_f(qo.x), f2tf_f(qo.y));
    float2 khv = make_float2(f2tf_f(ko.x), f2tf_f(ko.y));
    float2 klv = make_float2(f2tf_f(ko.x - khv.x), f2tf_f(ko.y - khv.y));
    float2 vr  = make_float2(f2tf_f(vv.x), f2tf_f(vv.y));

    size_t base_out = ((size_t)((b * H_ + h) * T_ + t)) * HD_ + p * 2;
    *(float2*)(q   + base_out) = qr;
    *(float2*)(khi + base_out) = khv;
    *(float2*)(klo + base_out) = klv;
    *(float2*)(v   + base_out) = vr;
}

// ================== Tensor-core flash attention (tf32, causal) ==================
// EXACT round-10/14 configuration (best known): K frags via ldmatrix,
// V via scalar LDS (interleaves with MMAs), kvissue after compute.
#define KV_TILE_F   (32 * 132)                  // 4224 floats
#define KV_STRIDE_F (3 * KV_TILE_F)             // 12672 floats per stage
#define ASM_BYTES   (3 * KV_STRIDE_F * 4)       // 152064 bytes

__global__ __launch_bounds__(256, 1) void attn_tc(
    const float* __restrict__ Qg, const float* __restrict__ Khig,
    const float* __restrict__ Klog, const float* __restrict__ Vg,
    float* __restrict__ Y)
{
    extern __shared__ float smn[];
    const uint32_t sbase = smem_u32(smn);
    const int qt = (int)gridDim.x - 1 - (int)blockIdx.x;   // heavy tiles first
    const int bh = blockIdx.y;
    const int b = bh >> 4, h = bh & 15;
    const int tid = threadIdx.x;
    const int w = tid >> 5, lane = tid & 31, g = lane >> 2, c = lane & 3;
    const size_t head = (size_t)bh * T_ * HD_;

    const int koff = ((lane & 7) + ((lane >> 4) & 1) * 8) * 132
                   + ((lane >> 3) & 1) * 4;

    // ---- stage Q tile (already tf32+scaled) into smem pitch 132, extract frags
    {
        const float4* Qt = (const float4*)(Qg + head + (size_t)qt * 128 * HD_);
        for (int i = tid; i < 128 * 32; i += 256) {
            int r = i >> 5, d4 = (i & 31) << 2;
            float4 qv = Qt[i];
            float* dst = smn + r * 132 + d4;
            dst[0] = qv.x; dst[1] = qv.y; dst[2] = qv.z; dst[3] = qv.w;
        }
    }
    __syncthreads();
    uint32_t qf[16][4];
    {
        const float* q0 = smn + (w * 16 + g) * 132 + c;
        #pragma unroll
        for (int ks = 0; ks < 16; ks++) {
            qf[ks][0] = __float_as_uint(q0[ks * 8]);
            qf[ks][1] = __float_as_uint(q0[ks * 8 + 8 * 132]);
            qf[ks][2] = __float_as_uint(q0[ks * 8 + 4]);
            qf[ks][3] = __float_as_uint(q0[ks * 8 + 8 * 132 + 4]);
        }
    }
    __syncthreads();

    float oacc[16][4];
    #pragma unroll
    for (int i = 0; i < 16; i++) {
        oacc[i][0] = 0.f; oacc[i][1] = 0.f; oacc[i][2] = 0.f; oacc[i][3] = 0.f;
    }
    float m0v = -1e30f, m1v = -1e30f, l0 = 0.f, l1 = 0.f;

    const int nkt = qt * 4 + 4;
    const int cr = tid >> 3;              // copy row 0..31
    const int cc = (tid & 7) << 2;        // copy col base (floats)

    auto kvissue = [&](int kt) {
        uint32_t dstb = sbase + (uint32_t)(kt % 3) * (KV_STRIDE_F * 4)
                      + cr * (132 * 4);
        size_t srcb = head + ((size_t)kt * 32 + cr) * HD_;
        #pragma unroll
        for (int ch = 0; ch < 4; ch++) {
            uint32_t dst = dstb + (cc + ch * 32) * 4;
            size_t src = srcb + cc + ch * 32;
            cp16(dst,                     Khig + src);
            cp16(dst + KV_TILE_F * 4,     Klog + src);
            cp16(dst + 2 * KV_TILE_F * 4, Vg + src);
        }
    };
    kvissue(0); cp_commit();
    if (nkt > 1) kvissue(1);
    cp_commit();

    const int rg0 = qt * 128 + w * 16 + g;
    const int rg8 = rg0 + 8;

    for (int kt = 0; kt < nkt; kt++) {
        cp_wait<1>();
        __syncthreads();
        const uint32_t Khs_u = sbase + (uint32_t)(kt % 3) * (KV_STRIDE_F * 4);
        const uint32_t Kls_u = Khs_u + KV_TILE_F * 4;
        const float* Vs = smn + (kt % 3) * KV_STRIDE_F + 2 * KV_TILE_F;

        // ---- S = Q*Khi + Q*Klo  (16x32 per warp), K frags via ldmatrix
        float sacc[4][4];
        #pragma unroll
        for (int nt = 0; nt < 4; nt++) {
            sacc[nt][0] = 0.f; sacc[nt][1] = 0.f;
            sacc[nt][2] = 0.f; sacc[nt][3] = 0.f;
        }
        #pragma unroll
        for (int ks = 0; ks < 16; ks++) {
            uint32_t bh4[2][4], bl4[2][4];
            ldsm4(bh4[0], Khs_u + (koff + ks * 8) * 4);
            ldsm4(bh4[1], Khs_u + (koff + 16 * 132 + ks * 8) * 4);
            ldsm4(bl4[0], Kls_u + (koff + ks * 8) * 4);
            ldsm4(bl4[1], Kls_u + (koff + 16 * 132 + ks * 8) * 4);
            #pragma unroll
            for (int nt = 0; nt < 4; nt++) {
                mma_tf32(sacc[nt], qf[ks], &bh4[nt >> 1][(nt & 1) * 2]);
                mma_tf32(sacc[nt], qf[ks], &bl4[nt >> 1][(nt & 1) * 2]);
            }
        }

        // ---- causal mask (only when tile can cross the diagonal for this warp)
        if (kt * 32 + 31 > qt * 128 + w * 16) {
            #pragma unroll
            for (int nt = 0; nt < 4; nt++) {
                int col = kt * 32 + nt * 8 + 2 * c;
                if (col     > rg0) sacc[nt][0] = -1e30f;
                if (col + 1 > rg0) sacc[nt][1] = -1e30f;
                if (col     > rg8) sacc[nt][2] = -1e30f;
                if (col + 1 > rg8) sacc[nt][3] = -1e30f;
            }
        }

        // ---- online softmax (rows g, g+8; reduce over quad lanes)
        float mx0 = -1e30f, mx1 = -1e30f;
        #pragma unroll
        for (int nt = 0; nt < 4; nt++) {
            mx0 = fmaxf(mx0, fmaxf(sacc[nt][0], sacc[nt][1]));
            mx1 = fmaxf(mx1, fmaxf(sacc[nt][2], sacc[nt][3]));
        }
        mx0 = fmaxf(mx0, __shfl_xor_sync(0xffffffffu, mx0, 1));
        mx0 = fmaxf(mx0, __shfl_xor_sync(0xffffffffu, mx0, 2));
        mx1 = fmaxf(mx1, __shfl_xor_sync(0xffffffffu, mx1, 1));
        mx1 = fmaxf(mx1, __shfl_xor_sync(0xffffffffu, mx1, 2));
        float nm0 = fmaxf(m0v, mx0), nm1 = fmaxf(m1v, mx1);
        float cf0 = expf_fast(m0v - nm0), cf1 = expf_fast(m1v - nm1);
        m0v = nm0; m1v = nm1;

        uint32_t pt[4][4];
        float rs0 = 0.f, rs1 = 0.f;
        #pragma unroll
        for (int nt = 0; nt < 4; nt++) {
            float p0 = expf_fast(sacc[nt][0] - nm0);
            float p1 = expf_fast(sacc[nt][1] - nm0);
            float p2 = expf_fast(sacc[nt][2] - nm1);
            float p3 = expf_fast(sacc[nt][3] - nm1);
            rs0 += p0 + p1; rs1 += p2 + p3;
            pt[nt][0] = f2tf(p0); pt[nt][1] = f2tf(p1);
            pt[nt][2] = f2tf(p2); pt[nt][3] = f2tf(p3);
        }
        rs0 += __shfl_xor_sync(0xffffffffu, rs0, 1);
        rs0 += __shfl_xor_sync(0xffffffffu, rs0, 2);
        rs1 += __shfl_xor_sync(0xffffffffu, rs1, 1);
        rs1 += __shfl_xor_sync(0xffffffffu, rs1, 2);
        l0 = l0 * cf0 + rs0;
        l1 = l1 * cf1 + rs1;

        #pragma unroll
        for (int nt2 = 0; nt2 < 16; nt2++) {
            oacc[nt2][0] *= cf0; oacc[nt2][1] *= cf0;
            oacc[nt2][2] *= cf1; oacc[nt2][3] *= cf1;
        }

        // ---- P acc-frag -> A-frag permutation via shfl, then O += P*V
        const int src  = (lane & 0x1C) | (c >> 1);
        const int src2 = src + 2;
        #pragma unroll
        for (int ks2 = 0; ks2 < 4; ks2++) {
            uint32_t e0 = __shfl_sync(0xffffffffu, pt[ks2][0], src);
            uint32_t e1 = __shfl_sync(0xffffffffu, pt[ks2][1], src);
            uint32_t e2 = __shfl_sync(0xffffffffu, pt[ks2][2], src);
            uint32_t e3 = __shfl_sync(0xffffffffu, pt[ks2][3], src);
            uint32_t f0 = __shfl_sync(0xffffffffu, pt[ks2][0], src2);
            uint32_t f1 = __shfl_sync(0xffffffffu, pt[ks2][1], src2);
            uint32_t f2x = __shfl_sync(0xffffffffu, pt[ks2][2], src2);
            uint32_t f3 = __shfl_sync(0xffffffffu, pt[ks2][3], src2);
            uint32_t af[4];
            af[0] = (c & 1) ? e1 : e0;
            af[1] = (c & 1) ? e3 : e2;
            af[2] = (c & 1) ? f1 : f0;
            af[3] = (c & 1) ? f3 : f2x;
            #pragma unroll
            for (int nt2 = 0; nt2 < 16; nt2++) {
                const float* vp = Vs + (ks2 * 8 + c) * 132 + nt2 * 8 + g;
                uint32_t bf[2] = { __float_as_uint(vp[0]),
                                   __float_as_uint(vp[4 * 132]) };
                mma_tf32(oacc[nt2], af, bf);
            }
        }

        // issue next KV stage AFTER compute
        if (kt + 2 < nkt) kvissue(kt + 2);
        cp_commit();
    }

    // ---- epilogue: normalize, tf32-round (feeds proj GEMM), store
    float inv0 = 1.f / l0, inv1 = 1.f / l1;
    float* Yb = Y + ((size_t)b * T_ + (size_t)qt * 128) * C_ + h * HD_;
    const int lr0 = w * 16 + g;
    #pragma unroll
    for (int nt2 = 0; nt2 < 16; nt2++) {
        *(float2*)(Yb + (size_t)lr0 * C_ + nt2 * 8 + 2 * c) =
            make_float2(f2tf_f(oacc[nt2][0] * inv0), f2tf_f(oacc[nt2][1] * inv0));
        *(float2*)(Yb + (size_t)(lr0 + 8) * C_ + nt2 * 8 + 2 * c) =
            make_float2(f2tf_f(oacc[nt2][2] * inv1), f2tf_f(oacc[nt2][3] * inv1));
    }
}

// ---------------- launch --------------------------------------------------------
extern "C" void kernel_launch(void* const* d_in, const int* in_sizes, int n_in,
                              void* d_out, int out_size)
{
    const float* x     = (const float*)d_in[0];
    const float* rope  = (const float*)d_in[1];
    const float* Wqkv  = (const float*)d_in[2];
    const float* Wproj = (const float*)d_in[3];
    float* out = (float*)d_out;

    float *qkv, *q, *khi, *klo, *v, *y, *xtf, *wqkvT, *wprojT;
    cudaGetSymbolAddress((void**)&qkv,    g_qkv);
    cudaGetSymbolAddress((void**)&q,      g_q);
    cudaGetSymbolAddress((void**)&khi,    g_khi);
    cudaGetSymbolAddress((void**)&klo,    g_klo);
    cudaGetSymbolAddress((void**)&v,      g_v);
    cudaGetSymbolAddress((void**)&y,      g_y);
    cudaGetSymbolAddress((void**)&xtf,    g_xtf);
    cudaGetSymbolAddress((void**)&wqkvT,  g_wqkvT);
    cudaGetSymbolAddress((void**)&wprojT, g_wprojT);

    cudaFuncSetAttribute(gemm_tf32, cudaFuncAttributeMaxDynamicSharedMemorySize,
                         GSM_BYTES);
    cudaFuncSetAttribute(attn_tc, cudaFuncAttributeMaxDynamicSharedMemorySize,
                         ASM_BYTES);

    // 0) operand prep
    tf32_round_kernel<<<(B_ * T_ * C_ / 4) / 256, 256>>>(x, xtf);
    transpose_kernel<<<dim3((3 * C_) / 32, C_ / 32), 256>>>(Wqkv, wqkvT, C_, 3 * C_);
    transpose_kernel<<<dim3(C_ / 32, C_ / 32), 256>>>(Wproj, wprojT, C_, C_);

    // 1) qkv = x @ Wqkv
    gemm_tf32<<<dim3((B_ * T_) / 128, (3 * C_) / 256), 512, GSM_BYTES>>>(
        xtf, wqkvT, qkv, B_ * T_, 3 * C_, C_);

    // 2) RoPE + split-K + tf32 rounding
    rope_kernel<<<(B_ * T_ * H_ * (HD_ / 2)) / 256, 256>>>(qkv, rope, q, khi, klo, v);

    // 3) tensor-core causal flash attention -> y
    attn_tc<<<dim3(T_ / 128, B_ * H_), 256, ASM_BYTES>>>(q, khi, klo, v, y);

    // 4) out = y @ Wproj
    gemm_tf32<<<dim3((B_ * T_) / 128, C_ / 256), 512, GSM_BYTES>>>(
        y, wprojT, out, B_ * T_, C_, C_);
}